// round 1
// baseline (speedup 1.0000x reference)
#include <cuda_runtime.h>

// self_attention_9225589752302 — round 0 baseline
// out[p,b,c,k] = sum_j V[p,b,c,j] * softmax_j( sum_c' J[p,b,c',j]*K[p,b,c',k] )
// P=8,B=8 -> 64 batches; C=64; N=H*W=1024.
// Flash-style fused kernel: grid (8 k-tiles, 64 batches), CTA = 256 threads,
// K-tile [64x128] resident, 16 j-tiles of 64 with online softmax over j per column k.

#define C_DIM 64
#define N_DIM 1024
#define BK 128
#define BJ 64
#define KSTRIDE 132   // 128 + 4 pad (keeps 16B alignment, breaks some conflicts)
#define SSTRIDE 132
#define JSTRIDE 68    // 64 + 4 pad
#define VSTRIDE 68
#define NTHREADS 256

#define SMEM_FLOATS (C_DIM*KSTRIDE + BJ*SSTRIDE + C_DIM*JSTRIDE + BJ*VSTRIDE + 3*BK)
#define SMEM_BYTES (SMEM_FLOATS * 4)

__global__ __launch_bounds__(NTHREADS)
void attn_fused_kernel(const float* __restrict__ Kg,
                       const float* __restrict__ Jg,
                       const float* __restrict__ Vg,
                       float* __restrict__ Og) {
    extern __shared__ float sm[];
    float* Kt   = sm;                         // [64][KSTRIDE]
    float* Ssm  = Kt  + C_DIM * KSTRIDE;      // [64][SSTRIDE]  score/P tile
    float* Jt   = Ssm + BJ * SSTRIDE;         // [64][JSTRIDE]  J tile, [c][j]
    float* Vt   = Jt  + C_DIM * JSTRIDE;      // [64][VSTRIDE]  V tile, TRANSPOSED [j][c]
    float* msm  = Vt  + BJ * VSTRIDE;         // [128] running max per k
    float* lsm  = msm + BK;                   // [128] running sum per k
    float* alph = lsm + BK;                   // [128] rescale factor per k

    const int tid = threadIdx.x;
    const int tx  = tid & 15;    // k-group: k0 = tx*8
    const int ty  = tid >> 4;    // j-group (GEMM1) / c-group (GEMM2): 4 per thread
    const int kt  = blockIdx.x;  // 0..7
    const int pb  = blockIdx.y;  // 0..63
    const long base  = (long)pb * C_DIM * N_DIM;
    const int  kbase = kt * BK;

    // Load resident K tile [c][k], coalesced
    #pragma unroll 4
    for (int idx = tid; idx < C_DIM * BK; idx += NTHREADS) {
        int c = idx >> 7, k = idx & 127;
        Kt[c * KSTRIDE + k] = Kg[base + (long)c * N_DIM + kbase + k];
    }
    if (tid < BK) { msm[tid] = -1e30f; lsm[tid] = 0.0f; }

    float acc[4][8];
    #pragma unroll
    for (int i = 0; i < 4; i++)
        #pragma unroll
        for (int j = 0; j < 8; j++) acc[i][j] = 0.0f;

    const int r0 = ty * 4;   // j offset in GEMM1, c offset in GEMM2
    const int k0 = tx * 8;

    for (int jt = 0; jt < N_DIM / BJ; jt++) {
        __syncthreads();  // prev GEMM2 done with Vt/Ssm

        // Load J tile [c][j] and V tile transposed [j][c]
        #pragma unroll 2
        for (int idx = tid; idx < C_DIM * BJ; idx += NTHREADS) {
            int c = idx >> 6, j = idx & 63;
            float jval = Jg[base + (long)c * N_DIM + jt * BJ + j];
            float vval = Vg[base + (long)c * N_DIM + jt * BJ + j];
            Jt[c * JSTRIDE + j] = jval;
            Vt[j * VSTRIDE + c] = vval;
        }
        __syncthreads();

        // ---- GEMM1: S[j,k] = sum_c J[c,j]*K[c,k], 4j x 8k per thread ----
        float s[4][8];
        #pragma unroll
        for (int i = 0; i < 4; i++)
            #pragma unroll
            for (int j = 0; j < 8; j++) s[i][j] = 0.0f;

        #pragma unroll 8
        for (int c = 0; c < C_DIM; c++) {
            float4 jv = *(const float4*)&Jt[c * JSTRIDE + r0];
            float4 ka = *(const float4*)&Kt[c * KSTRIDE + k0];
            float4 kb = *(const float4*)&Kt[c * KSTRIDE + k0 + 4];
            float jr[4] = {jv.x, jv.y, jv.z, jv.w};
            float kr[8] = {ka.x, ka.y, ka.z, ka.w, kb.x, kb.y, kb.z, kb.w};
            #pragma unroll
            for (int i = 0; i < 4; i++)
                #pragma unroll
                for (int j = 0; j < 8; j++)
                    s[i][j] = fmaf(jr[i], kr[j], s[i][j]);
        }
        // write S tile to smem
        #pragma unroll
        for (int i = 0; i < 4; i++) {
            *(float4*)&Ssm[(r0 + i) * SSTRIDE + k0]     = make_float4(s[i][0], s[i][1], s[i][2], s[i][3]);
            *(float4*)&Ssm[(r0 + i) * SSTRIDE + k0 + 4] = make_float4(s[i][4], s[i][5], s[i][6], s[i][7]);
        }
        __syncthreads();

        // ---- Online softmax over j (columns of S), one thread per k ----
        if (tid < BK) {
            const int k = tid;
            float mo = msm[k];
            float tm = -1e30f;
            #pragma unroll 8
            for (int j = 0; j < BJ; j++)
                tm = fmaxf(tm, Ssm[j * SSTRIDE + k]);
            float nm = fmaxf(mo, tm);
            float a  = __expf(mo - nm);
            float ts = 0.0f;
            #pragma unroll 8
            for (int j = 0; j < BJ; j++) {
                float e = __expf(Ssm[j * SSTRIDE + k] - nm);
                Ssm[j * SSTRIDE + k] = e;
                ts += e;
            }
            lsm[k]  = lsm[k] * a + ts;
            msm[k]  = nm;
            alph[k] = a;
        }
        __syncthreads();

        // ---- GEMM2: acc[c,k] = acc*alpha + sum_j V[c,j]*P[j,k], 4c x 8k ----
        float av[8];
        #pragma unroll
        for (int j = 0; j < 8; j++) av[j] = alph[k0 + j];
        #pragma unroll
        for (int i = 0; i < 4; i++)
            #pragma unroll
            for (int j = 0; j < 8; j++) acc[i][j] *= av[j];

        #pragma unroll 8
        for (int j = 0; j < BJ; j++) {
            float4 vv = *(const float4*)&Vt[j * VSTRIDE + r0];
            float4 pa = *(const float4*)&Ssm[j * SSTRIDE + k0];
            float4 pb2 = *(const float4*)&Ssm[j * SSTRIDE + k0 + 4];
            float vr[4] = {vv.x, vv.y, vv.z, vv.w};
            float pr[8] = {pa.x, pa.y, pa.z, pa.w, pb2.x, pb2.y, pb2.z, pb2.w};
            #pragma unroll
            for (int i = 0; i < 4; i++)
                #pragma unroll
                for (int jj = 0; jj < 8; jj++)
                    acc[i][jj] = fmaf(vr[i], pr[jj], acc[i][jj]);
        }
    }

    // ---- Epilogue: out[c,k] = acc / l[k] ----
    float rl[8];
    #pragma unroll
    for (int j = 0; j < 8; j++) rl[j] = 1.0f / lsm[k0 + j];
    #pragma unroll
    for (int i = 0; i < 4; i++) {
        long orow = base + (long)(r0 + i) * N_DIM + kbase + k0;
        *(float4*)&Og[orow]     = make_float4(acc[i][0]*rl[0], acc[i][1]*rl[1], acc[i][2]*rl[2], acc[i][3]*rl[3]);
        *(float4*)&Og[orow + 4] = make_float4(acc[i][4]*rl[4], acc[i][5]*rl[5], acc[i][6]*rl[6], acc[i][7]*rl[7]);
    }
}

extern "C" void kernel_launch(void* const* d_in, const int* in_sizes, int n_in,
                              void* d_out, int out_size) {
    const float* Kg = (const float*)d_in[0];  // K_set
    const float* Jg = (const float*)d_in[1];  // J_set
    const float* Vg = (const float*)d_in[2];  // V_set
    float* Og = (float*)d_out;

    cudaFuncSetAttribute(attn_fused_kernel,
                         cudaFuncAttributeMaxDynamicSharedMemorySize, SMEM_BYTES);

    dim3 grid(N_DIM / BK, 64);  // 8 k-tiles x 64 batches = 512 CTAs
    attn_fused_kernel<<<grid, NTHREADS, SMEM_BYTES>>>(Kg, Jg, Vg, Og);
}

// round 3
// speedup vs baseline: 3.8834x; 3.8834x over previous
#include <cuda_runtime.h>
#include <cuda_fp16.h>
#include <cuda_bf16.h>
#include <cstdint>

// self_attention_9225589752302 — round 2: mma.sync (portable PTX) flash attention
// GEMM1 fp16 hi/lo 3-pass split, GEMM2 bf16 hi/lo 3-pass split (P up to e^46 needs bf16 range).
// grid (8 k-tiles, 64 batches), 256 threads = 8 warps (4 m-strips x 2 j-halves).

#define NTHREADS 256

// smem byte offsets
#define KHI 0u            // K^T [k=128][c=64] fp16, 128B rows, swz ((k&7)<<4)
#define KLO 16384u
#define JHI 32768u        // J [c=64][j=128] fp16, 256B rows, swz ((c&7)<<4)
#define JLO 49152u
#define VHI 65536u        // V [c=64][j=128] bf16
#define VLO 81920u
#define LRED 98304u       // 384 f32: [0..255] partial row sums, [256..383] 1/l
#define SMEM_BYTES (98304u + 1536u)
#define STAGEOFF 32768u   // prologue stage f32 [64][132] (overlaps J/V, prologue-only)
#define OSTAGE 0u         // epilogue stage f32 [64][128] (overlaps K, epilogue-only)

static __device__ __forceinline__ uint32_t smem_u32(const void* p) {
    uint32_t a;
    asm("{ .reg .u64 t; cvta.to.shared.u64 t, %1; cvt.u32.u64 %0, t; }" : "=r"(a) : "l"(p));
    return a;
}
static __device__ __forceinline__ void ldsm4(uint32_t r[4], uint32_t a) {
    asm volatile("ldmatrix.sync.aligned.m8n8.x4.shared.b16 {%0,%1,%2,%3}, [%4];"
        : "=r"(r[0]), "=r"(r[1]), "=r"(r[2]), "=r"(r[3]) : "r"(a));
}
static __device__ __forceinline__ void ldsm4t(uint32_t r[4], uint32_t a) {
    asm volatile("ldmatrix.sync.aligned.m8n8.x4.trans.shared.b16 {%0,%1,%2,%3}, [%4];"
        : "=r"(r[0]), "=r"(r[1]), "=r"(r[2]), "=r"(r[3]) : "r"(a));
}
static __device__ __forceinline__ void mma_f16(float d[4], const uint32_t a[4], uint32_t b0, uint32_t b1) {
    asm("mma.sync.aligned.m16n8k16.row.col.f32.f16.f16.f32 "
        "{%0,%1,%2,%3}, {%4,%5,%6,%7}, {%8,%9}, {%0,%1,%2,%3};"
        : "+f"(d[0]), "+f"(d[1]), "+f"(d[2]), "+f"(d[3])
        : "r"(a[0]), "r"(a[1]), "r"(a[2]), "r"(a[3]), "r"(b0), "r"(b1));
}
static __device__ __forceinline__ void mma_bf16(float d[4], const uint32_t a[4], uint32_t b0, uint32_t b1) {
    asm("mma.sync.aligned.m16n8k16.row.col.f32.bf16.bf16.f32 "
        "{%0,%1,%2,%3}, {%4,%5,%6,%7}, {%8,%9}, {%0,%1,%2,%3};"
        : "+f"(d[0]), "+f"(d[1]), "+f"(d[2]), "+f"(d[3])
        : "r"(a[0]), "r"(a[1]), "r"(a[2]), "r"(a[3]), "r"(b0), "r"(b1));
}
static __device__ __forceinline__ uint32_t u32h2(__half2 h)         { return *(uint32_t*)&h; }
static __device__ __forceinline__ uint32_t u32b2(__nv_bfloat162 h)  { return *(uint32_t*)&h; }

__global__ __launch_bounds__(NTHREADS, 1)
void attn_mma_kernel(const float* __restrict__ Kg, const float* __restrict__ Jg,
                     const float* __restrict__ Vg, float* __restrict__ Og) {
    extern __shared__ char smem[];
    const uint32_t smb = smem_u32(smem);
    float* stage = (float*)(smem + STAGEOFF);
    float* lred  = (float*)(smem + LRED);
    float* ostage = (float*)(smem + OSTAGE);

    const int tid  = threadIdx.x;
    const int lane = tid & 31;
    const int wid  = tid >> 5;
    const int wm   = wid & 3;      // m-strip: rows 32*wm..+31
    const int wn   = wid >> 2;     // j-half: 64*wn..+63
    const int m0   = wm * 32;
    const int j0   = wn * 64;
    const unsigned base  = (unsigned)blockIdx.y * 65536u;
    const unsigned kbase = (unsigned)blockIdx.x * 128u;

    // ---------- Prologue: K^T tile (transpose + fp16 hi/lo split) ----------
    #pragma unroll
    for (int t = 0; t < 8; t++) {
        int flat = tid + t * 256;
        int c = flat >> 5, k4 = flat & 31;
        float4 v = *(const float4*)(Kg + base + (unsigned)c * 1024u + kbase + k4 * 4);
        float* s = stage + c * 132 + k4 * 4;
        s[0] = v.x; s[1] = v.y; s[2] = v.z; s[3] = v.w;
    }
    __syncthreads();
    #pragma unroll
    for (int t = 0; t < 16; t++) {
        int flat = tid + t * 256;
        int c = (flat & 31) * 2, k = flat >> 5;
        float x0 = stage[c * 132 + k], x1 = stage[(c + 1) * 132 + k];
        __half2 h = __floats2half2_rn(x0, x1);
        float2 hb = __half22float2(h);
        __half2 l = __floats2half2_rn(x0 - hb.x, x1 - hb.y);
        uint32_t off = (uint32_t)k * 128u + ((((uint32_t)c) * 2u) ^ ((((uint32_t)k) & 7u) << 4));
        *(uint32_t*)(smem + KHI + off) = u32h2(h);
        *(uint32_t*)(smem + KLO + off) = u32h2(l);
    }

    float D2[2][8][4];
    #pragma unroll
    for (int mt = 0; mt < 2; mt++)
        #pragma unroll
        for (int nt = 0; nt < 8; nt++)
            #pragma unroll
            for (int i = 0; i < 4; i++) D2[mt][nt][i] = 0.0f;
    float rsum[2][2] = {{0.0f, 0.0f}, {0.0f, 0.0f}};

    // lane-constant address pieces
    const uint32_t xorl  = (uint32_t)(lane & 7) << 4;
    const uint32_t aRow0 = (uint32_t)(m0 + (lane & 15)) * 128u;        // A ldsm row base (mt=0)
    const uint32_t aColH = (uint32_t)((lane >> 4) << 4);               // A col half (bytes)
    const uint32_t bRowJ = (uint32_t)((lane & 15)) * 256u;             // J ldsm row (c part, + ks*16*256)
    const uint32_t bColJ = (uint32_t)((lane >> 4) << 4);
    const uint32_t vRow  = (uint32_t)(lane & 7) * 256u;                // V ldsm row (+ nt*8*256)
    const uint32_t vColH = (uint32_t)((lane >> 3) << 4);

    for (int jt = 0; jt < 8; jt++) {
        __syncthreads();   // all warps done reading J/V of previous iter
        // ---------- load + convert J (fp16 hi/lo) and V (bf16 hi/lo) ----------
        #pragma unroll
        for (int t = 0; t < 8; t++) {
            int flat = tid + t * 256;
            int c = flat >> 5, j4 = flat & 31;
            unsigned g = base + (unsigned)c * 1024u + (unsigned)jt * 128u + j4 * 4;
            uint32_t soff = (uint32_t)c * 256u + ((((uint32_t)j4) * 8u) ^ ((((uint32_t)c) & 7u) << 4));
            float4 jv = *(const float4*)(Jg + g);
            __half2 jh0 = __floats2half2_rn(jv.x, jv.y), jh1 = __floats2half2_rn(jv.z, jv.w);
            float2 f0 = __half22float2(jh0), f1 = __half22float2(jh1);
            __half2 jl0 = __floats2half2_rn(jv.x - f0.x, jv.y - f0.y);
            __half2 jl1 = __floats2half2_rn(jv.z - f1.x, jv.w - f1.y);
            *(uint2*)(smem + JHI + soff) = make_uint2(u32h2(jh0), u32h2(jh1));
            *(uint2*)(smem + JLO + soff) = make_uint2(u32h2(jl0), u32h2(jl1));
            float4 vv = *(const float4*)(Vg + g);
            __nv_bfloat162 vh0 = __floats2bfloat162_rn(vv.x, vv.y), vh1 = __floats2bfloat162_rn(vv.z, vv.w);
            float2 g0 = __bfloat1622float2(vh0), g1 = __bfloat1622float2(vh1);
            __nv_bfloat162 vl0 = __floats2bfloat162_rn(vv.x - g0.x, vv.y - g0.y);
            __nv_bfloat162 vl1 = __floats2bfloat162_rn(vv.z - g1.x, vv.w - g1.y);
            *(uint2*)(smem + VHI + soff) = make_uint2(u32b2(vh0), u32b2(vh1));
            *(uint2*)(smem + VLO + soff) = make_uint2(u32b2(vl0), u32b2(vl1));
        }
        __syncthreads();

        #pragma unroll
        for (int h = 0; h < 2; h++) {
            // ---------- GEMM1: S[32 x 32] for this j-quarter-of-warp (h) ----------
            float S[2][4][4];
            #pragma unroll
            for (int mt = 0; mt < 2; mt++)
                #pragma unroll
                for (int nt = 0; nt < 4; nt++)
                    #pragma unroll
                    for (int i = 0; i < 4; i++) S[mt][nt][i] = 0.0f;

            #pragma unroll
            for (int ks = 0; ks < 4; ks++) {
                uint32_t ah0[4], ah1[4], al0[4], al1[4];
                uint32_t acol = ((uint32_t)(ks * 32) + aColH) ^ xorl;
                ldsm4(ah0, smb + KHI + aRow0 + acol);
                ldsm4(ah1, smb + KHI + aRow0 + 2048u + acol);
                ldsm4(al0, smb + KLO + aRow0 + acol);
                ldsm4(al1, smb + KLO + aRow0 + 2048u + acol);
                uint32_t jrow = (uint32_t)(ks * 16) * 256u + bRowJ;
                #pragma unroll
                for (int ntp = 0; ntp < 2; ntp++) {
                    uint32_t bh[4], bl[4];
                    uint32_t bcol = ((uint32_t)((j0 + h * 32 + ntp * 16) * 2) + bColJ) ^ xorl;
                    ldsm4t(bh, smb + JHI + jrow + bcol);
                    ldsm4t(bl, smb + JLO + jrow + bcol);
                    #pragma unroll
                    for (int q = 0; q < 2; q++) {
                        int nt = 2 * ntp + q;
                        mma_f16(S[0][nt], ah0, bh[2 * q], bh[2 * q + 1]);
                        mma_f16(S[1][nt], ah1, bh[2 * q], bh[2 * q + 1]);
                        mma_f16(S[0][nt], ah0, bl[2 * q], bl[2 * q + 1]);
                        mma_f16(S[1][nt], ah1, bl[2 * q], bl[2 * q + 1]);
                        mma_f16(S[0][nt], al0, bh[2 * q], bh[2 * q + 1]);
                        mma_f16(S[1][nt], al1, bh[2 * q], bh[2 * q + 1]);
                    }
                }
            }

            // ---------- softmax: P = exp(S), bf16 hi/lo A-fragments ----------
            uint32_t phi[2][2][4], plo[2][2][4];
            #pragma unroll
            for (int mt = 0; mt < 2; mt++)
                #pragma unroll
                for (int kl = 0; kl < 2; kl++)
                    #pragma unroll
                    for (int q = 0; q < 2; q++) {
                        const float* s = S[mt][2 * kl + q];
                        float p0 = __expf(s[0]), p1 = __expf(s[1]);
                        float p2 = __expf(s[2]), p3 = __expf(s[3]);
                        rsum[mt][0] += p0 + p1;
                        rsum[mt][1] += p2 + p3;
                        __nv_bfloat162 h01 = __floats2bfloat162_rn(p0, p1);
                        __nv_bfloat162 h23 = __floats2bfloat162_rn(p2, p3);
                        float2 b01 = __bfloat1622float2(h01), b23 = __bfloat1622float2(h23);
                        __nv_bfloat162 l01 = __floats2bfloat162_rn(p0 - b01.x, p1 - b01.y);
                        __nv_bfloat162 l23 = __floats2bfloat162_rn(p2 - b23.x, p3 - b23.y);
                        phi[mt][kl][2 * q]     = u32b2(h01);
                        phi[mt][kl][2 * q + 1] = u32b2(h23);
                        plo[mt][kl][2 * q]     = u32b2(l01);
                        plo[mt][kl][2 * q + 1] = u32b2(l23);
                    }

            // ---------- GEMM2: D2 += P x V^T over this half's j (k-steps 2h,2h+1) ----------
            uint32_t vcol = ((uint32_t)((j0 + h * 32) * 2) + vColH) ^ xorl;
            #pragma unroll
            for (int nt = 0; nt < 8; nt++) {
                uint32_t bh[4], bl[4];
                uint32_t vr = (uint32_t)(nt * 8) * 256u + vRow;
                ldsm4(bh, smb + VHI + vr + vcol);
                ldsm4(bl, smb + VLO + vr + vcol);
                #pragma unroll
                for (int mt = 0; mt < 2; mt++)
                    #pragma unroll
                    for (int kl = 0; kl < 2; kl++) {
                        mma_bf16(D2[mt][nt], phi[mt][kl], bh[2 * kl], bh[2 * kl + 1]);
                        mma_bf16(D2[mt][nt], phi[mt][kl], bl[2 * kl], bl[2 * kl + 1]);
                        mma_bf16(D2[mt][nt], plo[mt][kl], bh[2 * kl], bh[2 * kl + 1]);
                    }
            }
        }
    }

    // ---------- Epilogue ----------
    #pragma unroll
    for (int mt = 0; mt < 2; mt++)
        #pragma unroll
        for (int rr = 0; rr < 2; rr++) {
            float v = rsum[mt][rr];
            v += __shfl_xor_sync(0xffffffffu, v, 1);
            v += __shfl_xor_sync(0xffffffffu, v, 2);
            if ((lane & 3) == 0)
                lred[wn * 128 + m0 + mt * 16 + rr * 8 + (lane >> 2)] = v;
        }
    __syncthreads();   // all warps past GEMM1 (ostage overlaps K tiles)
    if (tid < 128) lred[256 + tid] = 1.0f / (lred[tid] + lred[128 + tid]);

    if (wn == 0) {
        #pragma unroll
        for (int mt = 0; mt < 2; mt++)
            #pragma unroll
            for (int nt = 0; nt < 8; nt++) {
                int c0 = nt * 8 + 2 * (lane & 3);
                int r = m0 + mt * 16 + (lane >> 2);
                ostage[c0 * 128 + r]           = D2[mt][nt][0];
                ostage[(c0 + 1) * 128 + r]     = D2[mt][nt][1];
                ostage[c0 * 128 + r + 8]       = D2[mt][nt][2];
                ostage[(c0 + 1) * 128 + r + 8] = D2[mt][nt][3];
            }
    }
    __syncthreads();
    if (wn == 1) {
        #pragma unroll
        for (int mt = 0; mt < 2; mt++)
            #pragma unroll
            for (int nt = 0; nt < 8; nt++) {
                int c0 = nt * 8 + 2 * (lane & 3);
                int r = m0 + mt * 16 + (lane >> 2);
                ostage[c0 * 128 + r]           += D2[mt][nt][0];
                ostage[(c0 + 1) * 128 + r]     += D2[mt][nt][1];
                ostage[c0 * 128 + r + 8]       += D2[mt][nt][2];
                ostage[(c0 + 1) * 128 + r + 8] += D2[mt][nt][3];
            }
    }
    __syncthreads();

    #pragma unroll
    for (int t = 0; t < 8; t++) {
        int flat = tid + t * 256;
        int c = flat >> 5, k4 = flat & 31;
        float4 v  = *(float4*)(ostage + c * 128 + k4 * 4);
        float4 iv = *(float4*)(lred + 256 + k4 * 4);
        v.x *= iv.x; v.y *= iv.y; v.z *= iv.z; v.w *= iv.w;
        *(float4*)(Og + base + (unsigned)c * 1024u + kbase + (unsigned)k4 * 4u) = v;
    }
}

extern "C" void kernel_launch(void* const* d_in, const int* in_sizes, int n_in,
                              void* d_out, int out_size) {
    const float* Kg = (const float*)d_in[0];
    const float* Jg = (const float*)d_in[1];
    const float* Vg = (const float*)d_in[2];
    float* Og = (float*)d_out;

    cudaFuncSetAttribute(attn_mma_kernel,
                         cudaFuncAttributeMaxDynamicSharedMemorySize, SMEM_BYTES);
    dim3 grid(8, 64);
    attn_mma_kernel<<<grid, NTHREADS, SMEM_BYTES>>>(Kg, Jg, Vg, Og);
}

// round 4
// speedup vs baseline: 3.9067x; 1.0060x over previous
#include <cuda_runtime.h>
#include <cuda_fp16.h>
#include <cuda_bf16.h>
#include <cstdint>

// self_attention_9225589752302 — round 3: 512 threads / 16 warps for latency hiding
// GEMM1 fp16 hi/lo 3-pass split, GEMM2 bf16 hi/lo 3-pass split.
// grid (8 k-tiles, 64 batches), 16 warps = 8 m-strips(16 rows) x 2 j-halves.

#define NTHREADS 512

// smem byte offsets
#define KHI 0u            // K^T [k=128][c=64] fp16, 128B rows, swz ((k&7)<<4)
#define KLO 16384u
#define JHI 32768u        // J [c=64][j=128] fp16, 256B rows, swz ((c&7)<<4)
#define JLO 49152u
#define VHI 65536u        // V [c=64][j=128] bf16
#define VLO 81920u
#define LRED 98304u       // 384 f32: [0..255] partial row sums, [256..383] 1/l
#define SMEM_BYTES (98304u + 1536u)
#define STAGEOFF 32768u   // prologue stage f32 [64][132] (overlaps J/V, prologue-only)
#define OSTAGE 0u         // epilogue stage f32 [64][128] (overlaps K, epilogue-only)

static __device__ __forceinline__ uint32_t smem_u32(const void* p) {
    uint32_t a;
    asm("{ .reg .u64 t; cvta.to.shared.u64 t, %1; cvt.u32.u64 %0, t; }" : "=r"(a) : "l"(p));
    return a;
}
static __device__ __forceinline__ void ldsm4(uint32_t r[4], uint32_t a) {
    asm volatile("ldmatrix.sync.aligned.m8n8.x4.shared.b16 {%0,%1,%2,%3}, [%4];"
        : "=r"(r[0]), "=r"(r[1]), "=r"(r[2]), "=r"(r[3]) : "r"(a));
}
static __device__ __forceinline__ void ldsm4t(uint32_t r[4], uint32_t a) {
    asm volatile("ldmatrix.sync.aligned.m8n8.x4.trans.shared.b16 {%0,%1,%2,%3}, [%4];"
        : "=r"(r[0]), "=r"(r[1]), "=r"(r[2]), "=r"(r[3]) : "r"(a));
}
static __device__ __forceinline__ void mma_f16(float d[4], const uint32_t a[4], uint32_t b0, uint32_t b1) {
    asm("mma.sync.aligned.m16n8k16.row.col.f32.f16.f16.f32 "
        "{%0,%1,%2,%3}, {%4,%5,%6,%7}, {%8,%9}, {%0,%1,%2,%3};"
        : "+f"(d[0]), "+f"(d[1]), "+f"(d[2]), "+f"(d[3])
        : "r"(a[0]), "r"(a[1]), "r"(a[2]), "r"(a[3]), "r"(b0), "r"(b1));
}
static __device__ __forceinline__ void mma_bf16(float d[4], const uint32_t a[4], uint32_t b0, uint32_t b1) {
    asm("mma.sync.aligned.m16n8k16.row.col.f32.bf16.bf16.f32 "
        "{%0,%1,%2,%3}, {%4,%5,%6,%7}, {%8,%9}, {%0,%1,%2,%3};"
        : "+f"(d[0]), "+f"(d[1]), "+f"(d[2]), "+f"(d[3])
        : "r"(a[0]), "r"(a[1]), "r"(a[2]), "r"(a[3]), "r"(b0), "r"(b1));
}
static __device__ __forceinline__ uint32_t u32h2(__half2 h)         { return *(uint32_t*)&h; }
static __device__ __forceinline__ uint32_t u32b2(__nv_bfloat162 h)  { return *(uint32_t*)&h; }

__global__ __launch_bounds__(NTHREADS, 1)
void attn_mma_kernel(const float* __restrict__ Kg, const float* __restrict__ Jg,
                     const float* __restrict__ Vg, float* __restrict__ Og) {
    extern __shared__ char smem[];
    const uint32_t smb = smem_u32(smem);
    float* stage = (float*)(smem + STAGEOFF);
    float* lred  = (float*)(smem + LRED);
    float* ostage = (float*)(smem + OSTAGE);

    const int tid  = threadIdx.x;
    const int lane = tid & 31;
    const int wid  = tid >> 5;
    const int wm   = wid & 7;      // m-strip: rows 16*wm..+15
    const int wn   = wid >> 3;     // j-half: 64*wn..+63
    const int m0   = wm * 16;
    const int j0   = wn * 64;
    const unsigned base  = (unsigned)blockIdx.y * 65536u;
    const unsigned kbase = (unsigned)blockIdx.x * 128u;

    // ---------- Prologue: K^T tile (transpose + fp16 hi/lo split) ----------
    #pragma unroll
    for (int t = 0; t < 4; t++) {
        int flat = tid + t * NTHREADS;
        int c = flat >> 5, k4 = flat & 31;
        float4 v = *(const float4*)(Kg + base + (unsigned)c * 1024u + kbase + k4 * 4);
        float* s = stage + c * 132 + k4 * 4;
        s[0] = v.x; s[1] = v.y; s[2] = v.z; s[3] = v.w;
    }
    __syncthreads();
    #pragma unroll
    for (int t = 0; t < 8; t++) {
        int flat = tid + t * NTHREADS;
        int c = (flat & 31) * 2, k = flat >> 5;
        float x0 = stage[c * 132 + k], x1 = stage[(c + 1) * 132 + k];
        __half2 h = __floats2half2_rn(x0, x1);
        float2 hb = __half22float2(h);
        __half2 l = __floats2half2_rn(x0 - hb.x, x1 - hb.y);
        uint32_t off = (uint32_t)k * 128u + ((((uint32_t)c) * 2u) ^ ((((uint32_t)k) & 7u) << 4));
        *(uint32_t*)(smem + KHI + off) = u32h2(h);
        *(uint32_t*)(smem + KLO + off) = u32h2(l);
    }

    float D2[8][4];
    #pragma unroll
    for (int nt = 0; nt < 8; nt++)
        #pragma unroll
        for (int i = 0; i < 4; i++) D2[nt][i] = 0.0f;
    float rsum[2] = {0.0f, 0.0f};

    // lane-constant address pieces
    const uint32_t xorl  = (uint32_t)(lane & 7) << 4;
    const uint32_t aRow0 = (uint32_t)(m0 + (lane & 15)) * 128u;        // A ldsm row base
    const uint32_t aColH = (uint32_t)((lane >> 4) << 4);               // A col half (bytes)
    const uint32_t bRowJ = (uint32_t)((lane & 15)) * 256u;             // J ldsm row
    const uint32_t bColJ = (uint32_t)((lane >> 4) << 4);
    const uint32_t vRow  = (uint32_t)(lane & 7) * 256u;                // V ldsm row
    const uint32_t vColH = (uint32_t)((lane >> 3) << 4);

    for (int jt = 0; jt < 8; jt++) {
        __syncthreads();   // all warps done reading J/V of previous iter
        // ---------- load + convert J (fp16 hi/lo) and V (bf16 hi/lo) ----------
        #pragma unroll
        for (int t = 0; t < 4; t++) {
            int flat = tid + t * NTHREADS;
            int c = flat >> 5, j4 = flat & 31;
            unsigned g = base + (unsigned)c * 1024u + (unsigned)jt * 128u + j4 * 4;
            uint32_t soff = (uint32_t)c * 256u + ((((uint32_t)j4) * 8u) ^ ((((uint32_t)c) & 7u) << 4));
            float4 jv = *(const float4*)(Jg + g);
            __half2 jh0 = __floats2half2_rn(jv.x, jv.y), jh1 = __floats2half2_rn(jv.z, jv.w);
            float2 f0 = __half22float2(jh0), f1 = __half22float2(jh1);
            __half2 jl0 = __floats2half2_rn(jv.x - f0.x, jv.y - f0.y);
            __half2 jl1 = __floats2half2_rn(jv.z - f1.x, jv.w - f1.y);
            *(uint2*)(smem + JHI + soff) = make_uint2(u32h2(jh0), u32h2(jh1));
            *(uint2*)(smem + JLO + soff) = make_uint2(u32h2(jl0), u32h2(jl1));
            float4 vv = *(const float4*)(Vg + g);
            __nv_bfloat162 vh0 = __floats2bfloat162_rn(vv.x, vv.y), vh1 = __floats2bfloat162_rn(vv.z, vv.w);
            float2 g0 = __bfloat1622float2(vh0), g1 = __bfloat1622float2(vh1);
            __nv_bfloat162 vl0 = __floats2bfloat162_rn(vv.x - g0.x, vv.y - g0.y);
            __nv_bfloat162 vl1 = __floats2bfloat162_rn(vv.z - g1.x, vv.w - g1.y);
            *(uint2*)(smem + VHI + soff) = make_uint2(u32b2(vh0), u32b2(vh1));
            *(uint2*)(smem + VLO + soff) = make_uint2(u32b2(vl0), u32b2(vl1));
        }
        __syncthreads();

        #pragma unroll
        for (int h = 0; h < 2; h++) {
            // ---------- GEMM1: S[16 x 32] for this j-quarter (h) ----------
            float S[4][4];
            #pragma unroll
            for (int nt = 0; nt < 4; nt++)
                #pragma unroll
                for (int i = 0; i < 4; i++) S[nt][i] = 0.0f;

            #pragma unroll
            for (int ks = 0; ks < 4; ks++) {
                uint32_t ah[4], al[4];
                uint32_t acol = ((uint32_t)(ks * 32) + aColH) ^ xorl;
                ldsm4(ah, smb + KHI + aRow0 + acol);
                ldsm4(al, smb + KLO + aRow0 + acol);
                uint32_t jrow = (uint32_t)(ks * 16) * 256u + bRowJ;
                #pragma unroll
                for (int ntp = 0; ntp < 2; ntp++) {
                    uint32_t bh[4], bl[4];
                    uint32_t bcol = ((uint32_t)((j0 + h * 32 + ntp * 16) * 2) + bColJ) ^ xorl;
                    ldsm4t(bh, smb + JHI + jrow + bcol);
                    ldsm4t(bl, smb + JLO + jrow + bcol);
                    #pragma unroll
                    for (int q = 0; q < 2; q++) {
                        int nt = 2 * ntp + q;
                        mma_f16(S[nt], ah, bh[2 * q], bh[2 * q + 1]);
                        mma_f16(S[nt], ah, bl[2 * q], bl[2 * q + 1]);
                        mma_f16(S[nt], al, bh[2 * q], bh[2 * q + 1]);
                    }
                }
            }

            // ---------- softmax: P = exp(S), bf16 hi/lo A-fragments ----------
            uint32_t phi[2][4], plo[2][4];
            #pragma unroll
            for (int kl = 0; kl < 2; kl++)
                #pragma unroll
                for (int q = 0; q < 2; q++) {
                    const float* s = S[2 * kl + q];
                    float p0 = __expf(s[0]), p1 = __expf(s[1]);
                    float p2 = __expf(s[2]), p3 = __expf(s[3]);
                    rsum[0] += p0 + p1;
                    rsum[1] += p2 + p3;
                    __nv_bfloat162 h01 = __floats2bfloat162_rn(p0, p1);
                    __nv_bfloat162 h23 = __floats2bfloat162_rn(p2, p3);
                    float2 b01 = __bfloat1622float2(h01), b23 = __bfloat1622float2(h23);
                    __nv_bfloat162 l01 = __floats2bfloat162_rn(p0 - b01.x, p1 - b01.y);
                    __nv_bfloat162 l23 = __floats2bfloat162_rn(p2 - b23.x, p3 - b23.y);
                    phi[kl][2 * q]     = u32b2(h01);
                    phi[kl][2 * q + 1] = u32b2(h23);
                    plo[kl][2 * q]     = u32b2(l01);
                    plo[kl][2 * q + 1] = u32b2(l23);
                }

            // ---------- GEMM2: D2 += P x V^T over this half's j ----------
            uint32_t vcol = ((uint32_t)((j0 + h * 32) * 2) + vColH) ^ xorl;
            #pragma unroll
            for (int nt = 0; nt < 8; nt++) {
                uint32_t bh[4], bl[4];
                uint32_t vr = (uint32_t)(nt * 8) * 256u + vRow;
                ldsm4(bh, smb + VHI + vr + vcol);
                ldsm4(bl, smb + VLO + vr + vcol);
                #pragma unroll
                for (int kl = 0; kl < 2; kl++) {
                    mma_bf16(D2[nt], phi[kl], bh[2 * kl], bh[2 * kl + 1]);
                    mma_bf16(D2[nt], phi[kl], bl[2 * kl], bl[2 * kl + 1]);
                    mma_bf16(D2[nt], plo[kl], bh[2 * kl], bh[2 * kl + 1]);
                }
            }
        }
    }

    // ---------- Epilogue ----------
    #pragma unroll
    for (int rr = 0; rr < 2; rr++) {
        float v = rsum[rr];
        v += __shfl_xor_sync(0xffffffffu, v, 1);
        v += __shfl_xor_sync(0xffffffffu, v, 2);
        if ((lane & 3) == 0)
            lred[wn * 128 + m0 + rr * 8 + (lane >> 2)] = v;
    }
    __syncthreads();   // all warps past GEMM1 (ostage overlaps K tiles)
    if (tid < 128) lred[256 + tid] = 1.0f / (lred[tid] + lred[128 + tid]);

    if (wn == 0) {
        #pragma unroll
        for (int nt = 0; nt < 8; nt++) {
            int c0 = nt * 8 + 2 * (lane & 3);
            int r = m0 + (lane >> 2);
            ostage[c0 * 128 + r]           = D2[nt][0];
            ostage[(c0 + 1) * 128 + r]     = D2[nt][1];
            ostage[c0 * 128 + r + 8]       = D2[nt][2];
            ostage[(c0 + 1) * 128 + r + 8] = D2[nt][3];
        }
    }
    __syncthreads();
    if (wn == 1) {
        #pragma unroll
        for (int nt = 0; nt < 8; nt++) {
            int c0 = nt * 8 + 2 * (lane & 3);
            int r = m0 + (lane >> 2);
            ostage[c0 * 128 + r]           += D2[nt][0];
            ostage[(c0 + 1) * 128 + r]     += D2[nt][1];
            ostage[c0 * 128 + r + 8]       += D2[nt][2];
            ostage[(c0 + 1) * 128 + r + 8] += D2[nt][3];
        }
    }
    __syncthreads();

    #pragma unroll
    for (int t = 0; t < 4; t++) {
        int flat = tid + t * NTHREADS;
        int c = flat >> 5, k4 = flat & 31;
        float4 v  = *(float4*)(ostage + c * 128 + k4 * 4);
        float4 iv = *(float4*)(lred + 256 + k4 * 4);
        v.x *= iv.x; v.y *= iv.y; v.z *= iv.z; v.w *= iv.w;
        *(float4*)(Og + base + (unsigned)c * 1024u + kbase + (unsigned)k4 * 4u) = v;
    }
}

extern "C" void kernel_launch(void* const* d_in, const int* in_sizes, int n_in,
                              void* d_out, int out_size) {
    const float* Kg = (const float*)d_in[0];
    const float* Jg = (const float*)d_in[1];
    const float* Vg = (const float*)d_in[2];
    float* Og = (float*)d_out;

    cudaFuncSetAttribute(attn_mma_kernel,
                         cudaFuncAttributeMaxDynamicSharedMemorySize, SMEM_BYTES);
    dim3 grid(8, 64);
    attn_mma_kernel<<<grid, NTHREADS, SMEM_BYTES>>>(Kg, Jg, Vg, Og);
}